// round 4
// baseline (speedup 1.0000x reference)
#include <cuda_runtime.h>
#include <math.h>

#define N_NODES 20000
#define N_EDGES 100000
#define MUL 128

// scratch: up-projected node features
// g_sup[n*128 + w]                 : scalar channel
// g_vup[n*384 + i*128 + w]         : vector channel, planar by component i
__device__ float g_sup[N_NODES * 128];
__device__ float g_vup[N_NODES * 384];

__device__ __forceinline__ float silu_n(float x) {
    float sig = 1.0f / (1.0f + __expf(-x));
    return x * sig * 1.6790390826f;
}

// ---------------------------------------------------------------------------
// Kernel 1: node up-projection.
//   s_up = (nf[:, :128] @ W_up_s) / sqrt(128)
//   v_up[i] = (nf_v[:, :, i] @ W_up_v) / sqrt(128)
// Block: 32 nodes, 256 threads. A packed float4 {s, vx, vy, vz} per (node,u).
// ---------------------------------------------------------------------------
__global__ __launch_bounds__(256, 1)
void node_up_kernel(const float* __restrict__ nf,
                    const float* __restrict__ Wus,
                    const float* __restrict__ Wuv) {
    extern __shared__ float sm[];
    float* sA = sm;              // 32*128*4 = 16384 floats (float4 per (n,u))
    float* sW = sm + 16384;      // 2 * 64*128 = 16384 floats

    int tid = threadIdx.x;
    int nb = blockIdx.x * 32;

    // Build A4: {s[u], v[u][0], v[u][1], v[u][2]}
    for (int p = tid; p < 4096; p += 256) {
        int n = p >> 7, u = p & 127;
        const float* row = nf + (size_t)(nb + n) * 512;
        float4 a;
        a.x = row[u];
        a.y = row[128 + 3 * u];
        a.z = row[128 + 3 * u + 1];
        a.w = row[128 + 3 * u + 2];
        ((float4*)sA)[p] = a;
    }

    float acc[16][4];
#pragma unroll
    for (int e = 0; e < 16; e++)
#pragma unroll
        for (int q = 0; q < 4; q++) acc[e][q] = 0.0f;

    int c = tid & 127;
    int n0 = (tid >> 7) * 16;

    for (int kk = 0; kk < 128; kk += 64) {
        __syncthreads();
        for (int p = tid; p < 8192; p += 256) {
            int kt = p >> 7, cc = p & 127;
            sW[p]        = Wus[(kk + kt) * 128 + cc];
            sW[8192 + p] = Wuv[(kk + kt) * 128 + cc];
        }
        __syncthreads();
#pragma unroll 4
        for (int kt = 0; kt < 64; kt++) {
            float ws = sW[kt * 128 + c];
            float wv = sW[8192 + kt * 128 + c];
#pragma unroll
            for (int e = 0; e < 16; e++) {
                float4 a = ((const float4*)sA)[(n0 + e) * 128 + kk + kt];
                acc[e][0] += a.x * ws;
                acc[e][1] += a.y * wv;
                acc[e][2] += a.z * wv;
                acc[e][3] += a.w * wv;
            }
        }
    }

    const float inv = 0.08838834764831845f;  // 1/sqrt(128)
#pragma unroll
    for (int e = 0; e < 16; e++) {
        int n = nb + n0 + e;
        g_sup[n * 128 + c]       = acc[e][0] * inv;
        g_vup[n * 384 + c]       = acc[e][1] * inv;
        g_vup[n * 384 + 128 + c] = acc[e][2] * inv;
        g_vup[n * 384 + 256 + c] = acc[e][3] * inv;
    }
}

// ---------------------------------------------------------------------------
// Kernel 2: fused edge pipeline.
// Per block: 32 edges.
//  Phase 1: MLP 8->64->64->64 (weights staged in smem, norms folded)
//  Phase 2: 4 chunks of the final MLP layer (w00,w01,w10,w11), fused with the
//           sender gather + tensor product, written as float4-packed A rows:
//           A4[e][k] = {mid_s[e][k], mid_vx[e][k], mid_vy[e][k], mid_vz[e][k]}
//           for k in [0,256). Scale constants folded:
//             a0:  sqrt(0.5)*sh0 * w00 * ss
//             a1i: sqrt(0.5)*sh1i * w01 * ss        (PW_1O/sqrt(3) = sqrt(0.5))
//             b1i: sqrt(0.5)*sh0 * w10 * vsi
//             b0:  sqrt(1/6) * w11 * sum_i(vsi*sh1i)
//  Phase 3: K=256 GEMM against W_out_s / W_out_v, store out (E x 512).
// ---------------------------------------------------------------------------
__global__ __launch_bounds__(256, 1)
void edge_fused_kernel(const float* __restrict__ edge_attrs,
                       const float* __restrict__ edge_feats,
                       const int*   __restrict__ edge_index,
                       const float* __restrict__ w0,
                       const float* __restrict__ w1,
                       const float* __restrict__ w2,
                       const float* __restrict__ w3,
                       const float* __restrict__ Wos,
                       const float* __restrict__ Wov,
                       float* __restrict__ out) {
    extern __shared__ float sm[];
    float* sA4  = sm;                       // 32*256*4 = 32768 floats
    float* sBuf = sm + 32768;               // 8704 floats (weight staging)
    float* sH   = sm + 32768 + 8704;        // 2*2048 floats (MLP act ping-pong)
    float* sEf  = sH + 4096;                // 256 floats
    float* sSh  = sEf + 256;                // 128 floats
    int*   sSend = (int*)(sSh + 128);       // 32 ints

    int tid = threadIdx.x;
    int eb = blockIdx.x * 32;

    // -------- phase 0: stage edge data + MLP weights (norm folded) --------
    if (tid < 32)  sSend[tid] = edge_index[eb + tid];          // sender row
    if (tid < 128) sSh[tid]   = edge_attrs[eb * 4 + tid];
    sEf[tid] = edge_feats[eb * 8 + tid];
    for (int p = tid; p < 512;  p += 256) sBuf[p]        = w0[p] * 0.3535533905932738f; // 1/sqrt(8)
    for (int p = tid; p < 4096; p += 256) sBuf[512 + p]  = w1[p] * 0.125f;              // 1/sqrt(64)
    for (int p = tid; p < 4096; p += 256) sBuf[4608 + p] = w2[p] * 0.125f;
    __syncthreads();

    // -------- phase 1: MLP layers 0..2 --------
    for (int p = tid; p < 2048; p += 256) {
        int e = p >> 6, j = p & 63;
        float a = 0.0f;
#pragma unroll
        for (int r = 0; r < 8; r++) a += sEf[e * 8 + r] * sBuf[r * 64 + j];
        sH[p] = silu_n(a);
    }
    __syncthreads();
    for (int p = tid; p < 2048; p += 256) {
        int e = p >> 6, j = p & 63;
        float a = 0.0f;
#pragma unroll 8
        for (int h = 0; h < 64; h++) a += sH[e * 64 + h] * sBuf[512 + h * 64 + j];
        sH[2048 + p] = silu_n(a);
    }
    __syncthreads();
    for (int p = tid; p < 2048; p += 256) {
        int e = p >> 6, j = p & 63;
        float a = 0.0f;
#pragma unroll 8
        for (int h = 0; h < 64; h++) a += sH[2048 + e * 64 + h] * sBuf[4608 + h * 64 + j];
        sH[p] = silu_n(a);   // h2 lives in region A
    }

    // -------- phase 2: last MLP layer fused with tensor product --------
    const float C05 = 0.7071067811865476f;   // sqrt(0.5)
    const float CB0 = 0.4082482904638631f;   // sqrt(1/6)
    int eL = tid >> 3;        // edge 0..31
    int kb = tid & 7;         // k base; thread covers k = kb + 8*i, i<16

    for (int ch = 0; ch < 4; ch++) {
        __syncthreads();       // prior sBuf/sH readers done
        for (int p = tid; p < 8192; p += 256) {
            int h = p >> 7, k = p & 127;
            sBuf[p] = w3[h * 512 + ch * 128 + k] * 0.125f;   // 1/sqrt(64)
        }
        __syncthreads();

        float acc16[16];
#pragma unroll
        for (int i = 0; i < 16; i++) acc16[i] = 0.0f;
#pragma unroll 4
        for (int h = 0; h < 64; h++) {
            float lh = sH[eL * 64 + h];
            const float* wrow = sBuf + h * 128 + kb;
#pragma unroll
            for (int i = 0; i < 16; i++) acc16[i] += lh * wrow[i * 8];
        }

        int snd = sSend[eL];
        float sh0 = sSh[eL * 4];
        if (ch == 0) {          // w00 -> a0 -> A4[.][k].x
#pragma unroll
            for (int i = 0; i < 16; i++) {
                int k = kb + i * 8;
                float ss = g_sup[snd * 128 + k];
                sA4[(eL * 256 + k) * 4] = C05 * sh0 * acc16[i] * ss;
            }
        } else if (ch == 1) {   // w01 -> a1 -> A4[.][k].{y,z,w}
#pragma unroll
            for (int i = 0; i < 16; i++) {
                int k = kb + i * 8;
                float ss = g_sup[snd * 128 + k];
                float t = C05 * acc16[i] * ss;
                int base = (eL * 256 + k) * 4;
                sA4[base + 1] = t * sSh[eL * 4 + 1];
                sA4[base + 2] = t * sSh[eL * 4 + 2];
                sA4[base + 3] = t * sSh[eL * 4 + 3];
            }
        } else if (ch == 2) {   // w10 -> b1 -> A4[.][128+k].{y,z,w}
#pragma unroll
            for (int i = 0; i < 16; i++) {
                int k = kb + i * 8;
                float t = C05 * sh0 * acc16[i];
                int base = (eL * 256 + 128 + k) * 4;
                sA4[base + 1] = t * g_vup[snd * 384 + k];
                sA4[base + 2] = t * g_vup[snd * 384 + 128 + k];
                sA4[base + 3] = t * g_vup[snd * 384 + 256 + k];
            }
        } else {                // w11 -> b0 -> A4[.][128+k].x
#pragma unroll
            for (int i = 0; i < 16; i++) {
                int k = kb + i * 8;
                float d = g_vup[snd * 384 + k]       * sSh[eL * 4 + 1]
                        + g_vup[snd * 384 + 128 + k] * sSh[eL * 4 + 2]
                        + g_vup[snd * 384 + 256 + k] * sSh[eL * 4 + 3];
                sA4[(eL * 256 + 128 + k) * 4] = CB0 * acc16[i] * d;
            }
        }
    }

    // -------- phase 3: output GEMM (K = 256) --------
    float acc[16][4];
#pragma unroll
    for (int e = 0; e < 16; e++)
#pragma unroll
        for (int q = 0; q < 4; q++) acc[e][q] = 0.0f;

    int c = tid & 127;
    int e0 = (tid >> 7) * 16;

    for (int kk = 0; kk < 256; kk += 32) {
        __syncthreads();       // at kk=0 this also fences phase-2 A4 writes
        for (int p = tid; p < 4096; p += 256) {
            int kt = p >> 7, cc = p & 127;
            sBuf[p]        = Wos[(kk + kt) * 128 + cc];
            sBuf[4096 + p] = Wov[(kk + kt) * 128 + cc];
        }
        __syncthreads();
#pragma unroll 4
        for (int kt = 0; kt < 32; kt++) {
            float ws = sBuf[kt * 128 + c];
            float wv = sBuf[4096 + kt * 128 + c];
#pragma unroll
            for (int e = 0; e < 16; e++) {
                float4 a = ((const float4*)sA4)[(e0 + e) * 256 + kk + kt];
                acc[e][0] += a.x * ws;
                acc[e][1] += a.y * wv;
                acc[e][2] += a.z * wv;
                acc[e][3] += a.w * wv;
            }
        }
    }

    const float inv16 = 0.0625f;   // 1/sqrt(256)
#pragma unroll
    for (int e = 0; e < 16; e++) {
        size_t row = (size_t)(eb + e0 + e) * 512;
        out[row + c]               = acc[e][0] * inv16;
        out[row + 128 + 3 * c]     = acc[e][1] * inv16;
        out[row + 128 + 3 * c + 1] = acc[e][2] * inv16;
        out[row + 128 + 3 * c + 2] = acc[e][3] * inv16;
    }
}

extern "C" void kernel_launch(void* const* d_in, const int* in_sizes, int n_in,
                              void* d_out, int out_size) {
    const float* nf  = (const float*)d_in[0];
    const float* ea  = (const float*)d_in[1];
    const float* ef  = (const float*)d_in[2];
    const int*   ei  = (const int*)  d_in[3];
    const float* Wus = (const float*)d_in[4];
    const float* Wuv = (const float*)d_in[5];
    const float* w0  = (const float*)d_in[6];
    const float* w1  = (const float*)d_in[7];
    const float* w2  = (const float*)d_in[8];
    const float* w3  = (const float*)d_in[9];
    const float* Wos = (const float*)d_in[10];
    const float* Wov = (const float*)d_in[11];
    float* out = (float*)d_out;

    const int smem_node = 32768 * 4;   // 128 KB
    const int smem_edge = 45984 * 4;   // ~179.6 KB
    cudaFuncSetAttribute((const void*)node_up_kernel,
                         cudaFuncAttributeMaxDynamicSharedMemorySize, smem_node);
    cudaFuncSetAttribute((const void*)edge_fused_kernel,
                         cudaFuncAttributeMaxDynamicSharedMemorySize, smem_edge);

    node_up_kernel<<<N_NODES / 32, 256, smem_node>>>(nf, Wus, Wuv);
    edge_fused_kernel<<<N_EDGES / 32, 256, smem_edge>>>(ea, ef, ei,
                                                        w0, w1, w2, w3,
                                                        Wos, Wov, out);
}

// round 7
// speedup vs baseline: 1.0118x; 1.0118x over previous
#include <cuda_runtime.h>
#include <math.h>

#define N_NODES 20000
#define N_EDGES 100000

// scratch: up-projected node features
__device__ __align__(256) float g_sup[N_NODES * 128];
__device__ __align__(256) float g_vup[N_NODES * 384];   // planar: [n][comp][u]

__device__ __forceinline__ float silu_n(float x) {
    return x * 1.6790390826f / (1.0f + __expf(-x));
}
__device__ __forceinline__ void fma4(float4& a, float s, float4 w) {
    a.x += s * w.x; a.y += s * w.y; a.z += s * w.z; a.w += s * w.w;
}
__device__ __forceinline__ float4 scl4(float4 a, float s) {
    return make_float4(a.x * s, a.y * s, a.z * s, a.w * s);
}
#define F4(p) (*reinterpret_cast<const float4*>(p))
#define F4W(p) (*reinterpret_cast<float4*>(p))

// ---------------------------------------------------------------------------
// Kernel 1: node up-projection, 4node x 4col x 4comp register tile.
// ---------------------------------------------------------------------------
__global__ __launch_bounds__(256, 1)
void node_up_kernel(const float* __restrict__ nf,
                    const float* __restrict__ Wus,
                    const float* __restrict__ Wuv) {
    extern __shared__ float sm[];
    float* sA = sm;          // 16384 floats: float4{s,vx,vy,vz} per (n,u)
    float* sW = sm + 16384;  // 16384: Wus chunk | Wuv chunk (64 k x 128 c each)

    int tid = threadIdx.x;
    int nb = blockIdx.x * 32;
    int c4 = (tid & 31) * 4;
    int ng = tid >> 5;       // 8 groups x 4 nodes

    for (int p = tid; p < 4096; p += 256) {
        int n = p >> 7, u = p & 127;
        const float* row = nf + (size_t)(nb + n) * 512;
        float4 a;
        a.x = row[u];
        a.y = row[128 + 3 * u];
        a.z = row[129 + 3 * u];
        a.w = row[130 + 3 * u];
        ((float4*)sA)[p] = a;
    }

    float4 accS[4], accX[4], accY[4], accZ[4];
#pragma unroll
    for (int e = 0; e < 4; e++) {
        accS[e] = make_float4(0.f, 0.f, 0.f, 0.f);
        accX[e] = accS[e]; accY[e] = accS[e]; accZ[e] = accS[e];
    }

    for (int kk = 0; kk < 128; kk += 64) {
        __syncthreads();
        for (int p = tid; p < 8192; p += 256) {
            int kt = p >> 7, cc = p & 127;
            sW[p]        = Wus[(kk + kt) * 128 + cc];
            sW[8192 + p] = Wuv[(kk + kt) * 128 + cc];
        }
        __syncthreads();
#pragma unroll 4
        for (int kt = 0; kt < 64; kt++) {
            float4 ws = F4(&sW[kt * 128 + c4]);
            float4 wv = F4(&sW[8192 + kt * 128 + c4]);
#pragma unroll
            for (int e = 0; e < 4; e++) {
                float4 a = ((const float4*)sA)[(ng * 4 + e) * 128 + kk + kt];
                fma4(accS[e], a.x, ws);
                fma4(accX[e], a.y, wv);
                fma4(accY[e], a.z, wv);
                fma4(accZ[e], a.w, wv);
            }
        }
    }

    const float inv = 0.08838834764831845f;  // 1/sqrt(128)
#pragma unroll
    for (int e = 0; e < 4; e++) {
        int n = nb + ng * 4 + e;
        F4W(&g_sup[n * 128 + c4])       = scl4(accS[e], inv);
        F4W(&g_vup[n * 384 + c4])       = scl4(accX[e], inv);
        F4W(&g_vup[n * 384 + 128 + c4]) = scl4(accY[e], inv);
        F4W(&g_vup[n * 384 + 256 + c4]) = scl4(accZ[e], inv);
    }
}

// ---------------------------------------------------------------------------
// Kernel 2: fused edge pipeline, register-tiled everywhere.
// smem (floats):
//   sA4   [0      .. 32768)  A rows float4-packed: {s, vx, vy, vz} per (e,k)
//   R     [32768  .. 49152)  staging (w0 | w1t | w2t), (w3 halves), (Wout)
//   sH    [49152  .. 53248)  MLP activations ping-pong (2 x 2048)
//   sEf   [53248  .. 53504)
//   sSh   [53504  .. 53632)
//   sSend [53632  .. 53664)
// total 53664 floats = 214656 B
// ---------------------------------------------------------------------------
__global__ __launch_bounds__(256, 1)
void edge_fused_kernel(const float* __restrict__ edge_attrs,
                       const float* __restrict__ edge_feats,
                       const int*   __restrict__ edge_index,
                       const float* __restrict__ w0,
                       const float* __restrict__ w1,
                       const float* __restrict__ w2,
                       const float* __restrict__ w3,
                       const float* __restrict__ Wos,
                       const float* __restrict__ Wov,
                       float* __restrict__ out) {
    extern __shared__ float sm[];
    float* sA4  = sm;
    float* R    = sm + 32768;
    float* sH   = sm + 49152;
    float* sEf  = sm + 53248;
    float* sSh  = sm + 53504;
    int*   sSend = (int*)(sm + 53632);

    int tid = threadIdx.x;
    int eb = blockIdx.x * 32;

    // -------- stage edge data + MLP weights (norms folded, w1/w2 transposed,
    //          transposed rows padded to 68 to avoid LDS bank conflicts) -----
    if (tid < 32)  sSend[tid] = edge_index[eb + tid];
    if (tid < 128) sSh[tid]   = edge_attrs[eb * 4 + tid];
    sEf[tid] = edge_feats[eb * 8 + tid];
    for (int p = tid; p < 512; p += 256) R[p] = w0[p] * 0.3535533905932738f;    // 1/sqrt(8)
    for (int p = tid; p < 4096; p += 256) {
        int h = p >> 6, j = p & 63;
        R[512  + j * 68 + h] = w1[p] * 0.125f;                                   // 1/sqrt(64)
        R[4864 + j * 68 + h] = w2[p] * 0.125f;
    }
    __syncthreads();

    // -------- phase 1: MLP layer 0 (8 -> 64) --------
    for (int p = tid; p < 2048; p += 256) {
        int e = p >> 6, j = p & 63;
        float a = 0.0f;
#pragma unroll
        for (int r = 0; r < 8; r++) a += sEf[e * 8 + r] * R[r * 64 + j];
        sH[p] = silu_n(a);
    }
    __syncthreads();

    // -------- layers 1,2 (64 -> 64), transposed W, 8-edge register tile ----
    {
        int eg1 = tid >> 6;         // 0..3, 8 edges each
        int j1  = tid & 63;
        float acc8[8];
#pragma unroll
        for (int e = 0; e < 8; e++) acc8[e] = 0.0f;
#pragma unroll 4
        for (int hh = 0; hh < 64; hh += 4) {
            float4 w4 = F4(&R[512 + j1 * 68 + hh]);
#pragma unroll
            for (int e = 0; e < 8; e++) {
                float4 h4 = F4(&sH[(eg1 * 8 + e) * 64 + hh]);
                acc8[e] += h4.x * w4.x + h4.y * w4.y + h4.z * w4.z + h4.w * w4.w;
            }
        }
        __syncthreads();
#pragma unroll
        for (int e = 0; e < 8; e++)
            sH[2048 + (eg1 * 8 + e) * 64 + j1] = silu_n(acc8[e]);
        __syncthreads();

#pragma unroll
        for (int e = 0; e < 8; e++) acc8[e] = 0.0f;
#pragma unroll 4
        for (int hh = 0; hh < 64; hh += 4) {
            float4 w4 = F4(&R[4864 + j1 * 68 + hh]);
#pragma unroll
            for (int e = 0; e < 8; e++) {
                float4 h4 = F4(&sH[2048 + (eg1 * 8 + e) * 64 + hh]);
                acc8[e] += h4.x * w4.x + h4.y * w4.y + h4.z * w4.z + h4.w * w4.w;
            }
        }
        __syncthreads();
#pragma unroll
        for (int e = 0; e < 8; e++)
            sH[(eg1 * 8 + e) * 64 + j1] = silu_n(acc8[e]);   // h2 -> region A
    }

    // -------- phase 2: last MLP layer + tensor product, float4-packed ------
    const float C05 = 0.7071067811865476f;   // sqrt(0.5) (= PW_1O/sqrt(3) too)
    const float CB0 = 0.4082482904638631f;   // sqrt(1/6)
    int eg = tid >> 5;            // 0..7 -> 4 edges each
    int c4 = (tid & 31) * 4;      // k/col quad

    for (int half = 0; half < 2; half++) {
        __syncthreads();          // prior R readers done
        for (int p = tid; p < 16384; p += 256)
            R[p] = w3[(p >> 8) * 512 + half * 256 + (p & 255)] * 0.125f;
        __syncthreads();

        float4 accA[4], accB[4];
#pragma unroll
        for (int e = 0; e < 4; e++) {
            accA[e] = make_float4(0.f, 0.f, 0.f, 0.f);
            accB[e] = accA[e];
        }
#pragma unroll 2
        for (int hh = 0; hh < 64; hh += 4) {
            float4 wa0 = F4(&R[(hh + 0) * 256 + c4]);
            float4 wa1 = F4(&R[(hh + 1) * 256 + c4]);
            float4 wa2 = F4(&R[(hh + 2) * 256 + c4]);
            float4 wa3 = F4(&R[(hh + 3) * 256 + c4]);
            float4 wb0 = F4(&R[(hh + 0) * 256 + 128 + c4]);
            float4 wb1 = F4(&R[(hh + 1) * 256 + 128 + c4]);
            float4 wb2 = F4(&R[(hh + 2) * 256 + 128 + c4]);
            float4 wb3 = F4(&R[(hh + 3) * 256 + 128 + c4]);
#pragma unroll
            for (int e = 0; e < 4; e++) {
                float4 h4 = F4(&sH[(eg * 4 + e) * 64 + hh]);
                fma4(accA[e], h4.x, wa0); fma4(accA[e], h4.y, wa1);
                fma4(accA[e], h4.z, wa2); fma4(accA[e], h4.w, wa3);
                fma4(accB[e], h4.x, wb0); fma4(accB[e], h4.y, wb1);
                fma4(accB[e], h4.z, wb2); fma4(accB[e], h4.w, wb3);
            }
        }

#pragma unroll
        for (int e = 0; e < 4; e++) {
            int ee = eg * 4 + e;
            int snd = sSend[ee];
            float4 sh = F4(&sSh[ee * 4]);
            float aA[4] = {accA[e].x, accA[e].y, accA[e].z, accA[e].w};
            float aB[4] = {accB[e].x, accB[e].y, accB[e].z, accB[e].w};
            if (half == 0) {   // aA = w00, aB = w01
                float4 ss4 = F4(&g_sup[snd * 128 + c4]);
                float ss[4] = {ss4.x, ss4.y, ss4.z, ss4.w};
#pragma unroll
                for (int j = 0; j < 4; j++) {
                    float t0 = C05 * sh.x * aA[j] * ss[j];
                    float t1 = C05 * aB[j] * ss[j];
                    ((float4*)sA4)[ee * 256 + c4 + j] =
                        make_float4(t0, t1 * sh.y, t1 * sh.z, t1 * sh.w);
                }
            } else {           // aA = w10, aB = w11
                float4 x4 = F4(&g_vup[snd * 384 + c4]);
                float4 y4 = F4(&g_vup[snd * 384 + 128 + c4]);
                float4 z4 = F4(&g_vup[snd * 384 + 256 + c4]);
                float vx[4] = {x4.x, x4.y, x4.z, x4.w};
                float vy[4] = {y4.x, y4.y, y4.z, y4.w};
                float vz[4] = {z4.x, z4.y, z4.z, z4.w};
#pragma unroll
                for (int j = 0; j < 4; j++) {
                    float t = C05 * sh.x * aA[j];
                    float d = vx[j] * sh.y + vy[j] * sh.z + vz[j] * sh.w;
                    ((float4*)sA4)[ee * 256 + 128 + c4 + j] =
                        make_float4(CB0 * aB[j] * d, t * vx[j], t * vy[j], t * vz[j]);
                }
            }
        }
    }

    // -------- phase 3: output GEMM (K = 256), 4e x 4c x 4comp tile ---------
    float4 accS[4], accVx[4], accVy[4], accVz[4];
#pragma unroll
    for (int e = 0; e < 4; e++) {
        accS[e]  = make_float4(0.f, 0.f, 0.f, 0.f);
        accVx[e] = accS[e]; accVy[e] = accS[e]; accVz[e] = accS[e];
    }

    for (int kk = 0; kk < 256; kk += 64) {
        __syncthreads();          // at kk=0 also fences phase-2 sA4 writes
        for (int p = tid; p < 8192; p += 256) {
            int kt = p >> 7, cc = p & 127;
            R[p]        = Wos[(kk + kt) * 128 + cc];
            R[8192 + p] = Wov[(kk + kt) * 128 + cc];
        }
        __syncthreads();
#pragma unroll 4
        for (int kt = 0; kt < 64; kt++) {
            float4 ws = F4(&R[kt * 128 + c4]);
            float4 wv = F4(&R[8192 + kt * 128 + c4]);
#pragma unroll
            for (int e = 0; e < 4; e++) {
                float4 a = ((const float4*)sA4)[(eg * 4 + e) * 256 + kk + kt];
                fma4(accS[e],  a.x, ws);
                fma4(accVx[e], a.y, wv);
                fma4(accVy[e], a.z, wv);
                fma4(accVz[e], a.w, wv);
            }
        }
    }

    const float inv16 = 0.0625f;  // 1/sqrt(256)
#pragma unroll
    for (int e = 0; e < 4; e++) {
        size_t row = (size_t)(eb + eg * 4 + e) * 512;
        float4 S = scl4(accS[e],  inv16);
        float4 X = scl4(accVx[e], inv16);
        float4 Y = scl4(accVy[e], inv16);
        float4 Z = scl4(accVz[e], inv16);
        F4W(&out[row + c4]) = S;
        // v layout: out[row + 128 + 3*c + comp]; cols c4..c4+3 -> 12 floats
        F4W(&out[row + 128 + 3 * c4 + 0]) = make_float4(X.x, Y.x, Z.x, X.y);
        F4W(&out[row + 128 + 3 * c4 + 4]) = make_float4(Y.y, Z.y, X.z, Y.z);
        F4W(&out[row + 128 + 3 * c4 + 8]) = make_float4(Z.z, X.w, Y.w, Z.w);
    }
}

extern "C" void kernel_launch(void* const* d_in, const int* in_sizes, int n_in,
                              void* d_out, int out_size) {
    const float* nf  = (const float*)d_in[0];
    const float* ea  = (const float*)d_in[1];
    const float* ef  = (const float*)d_in[2];
    const int*   ei  = (const int*)  d_in[3];
    const float* Wus = (const float*)d_in[4];
    const float* Wuv = (const float*)d_in[5];
    const float* w0  = (const float*)d_in[6];
    const float* w1  = (const float*)d_in[7];
    const float* w2  = (const float*)d_in[8];
    const float* w3  = (const float*)d_in[9];
    const float* Wos = (const float*)d_in[10];
    const float* Wov = (const float*)d_in[11];
    float* out = (float*)d_out;

    const int smem_node = 32768 * 4;   // 128 KB
    const int smem_edge = 53664 * 4;   // ~209.6 KB
    cudaFuncSetAttribute((const void*)node_up_kernel,
                         cudaFuncAttributeMaxDynamicSharedMemorySize, smem_node);
    cudaFuncSetAttribute((const void*)edge_fused_kernel,
                         cudaFuncAttributeMaxDynamicSharedMemorySize, smem_edge);

    node_up_kernel<<<N_NODES / 32, 256, smem_node>>>(nf, Wus, Wuv);
    edge_fused_kernel<<<N_EDGES / 32, 256, smem_edge>>>(ea, ef, ei,
                                                        w0, w1, w2, w3,
                                                        Wos, Wov, out);
}

// round 10
// speedup vs baseline: 1.5405x; 1.5225x over previous
#include <cuda_runtime.h>
#include <math.h>

#define N_NODES 20000
#define N_EDGES 100000
#define EB 16              // edges per block

// scratch: up-projected node features
__device__ __align__(256) float g_sup[N_NODES * 128];
__device__ __align__(256) float g_vup[N_NODES * 384];   // planar: [n][comp][u]

__device__ __forceinline__ float silu_n(float x) {
    return x * 1.6790390826f / (1.0f + __expf(-x));
}
__device__ __forceinline__ void fma4(float4& a, float s, float4 w) {
    a.x += s * w.x; a.y += s * w.y; a.z += s * w.z; a.w += s * w.w;
}
__device__ __forceinline__ float4 scl4(float4 a, float s) {
    return make_float4(a.x * s, a.y * s, a.z * s, a.w * s);
}
#define F4(p) (*reinterpret_cast<const float4*>(p))
#define F4W(p) (*reinterpret_cast<float4*>(p))

// ---------------------------------------------------------------------------
// Kernel 1: node up-projection, 4node x 4col x 4comp register tile.
// smem = 16384 (A4) + 8192 (W chunk) = 24576 floats = 96 KB -> 2 CTAs/SM
// ---------------------------------------------------------------------------
__global__ __launch_bounds__(256, 2)
void node_up_kernel(const float* __restrict__ nf,
                    const float* __restrict__ Wus,
                    const float* __restrict__ Wuv) {
    extern __shared__ float sm[];
    float* sA = sm;          // 16384 floats: float4{s,vx,vy,vz} per (n,u)
    float* sW = sm + 16384;  // 8192: Wus chunk | Wuv chunk (32 k x 128 c each)

    int tid = threadIdx.x;
    int nb = blockIdx.x * 32;
    int c4 = (tid & 31) * 4;
    int ng = tid >> 5;       // 8 groups x 4 nodes

    for (int p = tid; p < 4096; p += 256) {
        int n = p >> 7, u = p & 127;
        const float* row = nf + (size_t)(nb + n) * 512;
        float4 a;
        a.x = row[u];
        a.y = row[128 + 3 * u];
        a.z = row[129 + 3 * u];
        a.w = row[130 + 3 * u];
        ((float4*)sA)[p] = a;
    }

    float4 accS[4], accX[4], accY[4], accZ[4];
#pragma unroll
    for (int e = 0; e < 4; e++) {
        accS[e] = make_float4(0.f, 0.f, 0.f, 0.f);
        accX[e] = accS[e]; accY[e] = accS[e]; accZ[e] = accS[e];
    }

    for (int kk = 0; kk < 128; kk += 32) {
        __syncthreads();
        for (int p = tid; p < 4096; p += 256) {
            int kt = p >> 7, cc = p & 127;
            sW[p]        = Wus[(kk + kt) * 128 + cc];
            sW[4096 + p] = Wuv[(kk + kt) * 128 + cc];
        }
        __syncthreads();
#pragma unroll 4
        for (int kt = 0; kt < 32; kt++) {
            float4 ws = F4(&sW[kt * 128 + c4]);
            float4 wv = F4(&sW[4096 + kt * 128 + c4]);
#pragma unroll
            for (int e = 0; e < 4; e++) {
                float4 a = ((const float4*)sA)[(ng * 4 + e) * 128 + kk + kt];
                fma4(accS[e], a.x, ws);
                fma4(accX[e], a.y, wv);
                fma4(accY[e], a.z, wv);
                fma4(accZ[e], a.w, wv);
            }
        }
    }

    const float inv = 0.08838834764831845f;  // 1/sqrt(128)
#pragma unroll
    for (int e = 0; e < 4; e++) {
        int n = nb + ng * 4 + e;
        F4W(&g_sup[n * 128 + c4])       = scl4(accS[e], inv);
        F4W(&g_vup[n * 384 + c4])       = scl4(accX[e], inv);
        F4W(&g_vup[n * 384 + 128 + c4]) = scl4(accY[e], inv);
        F4W(&g_vup[n * 384 + 256 + c4]) = scl4(accZ[e], inv);
    }
}

// ---------------------------------------------------------------------------
// Kernel 2: fused edge pipeline, 16 edges/block, 2 CTAs/SM.
// smem (floats):
//   sA4   [0     .. 16384)  A rows float4-packed {s,vx,vy,vz} per (e,k)
//   R     [16384 .. 25600)  staging (max 9216: w0|w1t|w2t; w3 quarter=8192;
//                           Wout 32-k chunk = 8192)
//   sH    [25600 .. 27648)  MLP activations (h0/h2 @0, h1 @1024)
//   sEf   [27648 .. 27776)
//   sSh   [27776 .. 27840)
//   sSend [27840 .. 27856)
// total 27856 floats = 111424 B  -> 2 CTAs/SM
// ---------------------------------------------------------------------------
__global__ __launch_bounds__(256, 2)
void edge_fused_kernel(const float* __restrict__ edge_attrs,
                       const float* __restrict__ edge_feats,
                       const int*   __restrict__ edge_index,
                       const float* __restrict__ w0,
                       const float* __restrict__ w1,
                       const float* __restrict__ w2,
                       const float* __restrict__ w3,
                       const float* __restrict__ Wos,
                       const float* __restrict__ Wov,
                       float* __restrict__ out) {
    extern __shared__ float sm[];
    float* sA4  = sm;
    float* R    = sm + 16384;
    float* sH   = sm + 25600;
    float* sEf  = sm + 27648;
    float* sSh  = sm + 27776;
    int*   sSend = (int*)(sm + 27840);

    int tid = threadIdx.x;
    int eb = blockIdx.x * EB;

    // -------- stage edge data + MLP weights (norms folded; w1/w2 transposed,
    //          rows padded to stride 68) --------
    if (tid < EB)     sSend[tid] = edge_index[eb + tid];
    if (tid < EB * 4) sSh[tid]   = edge_attrs[eb * 4 + tid];
    if (tid < EB * 8) sEf[tid]   = edge_feats[eb * 8 + tid];
    for (int p = tid; p < 512; p += 256) R[p] = w0[p] * 0.3535533905932738f;  // 1/sqrt(8)
    for (int p = tid; p < 4096; p += 256) {
        int h = p >> 6, j = p & 63;
        R[512  + j * 68 + h] = w1[p] * 0.125f;                                 // 1/sqrt(64)
        R[4864 + j * 68 + h] = w2[p] * 0.125f;
    }
    __syncthreads();

    // -------- phase 1: MLP layer 0 (8 -> 64) --------
    for (int p = tid; p < EB * 64; p += 256) {
        int e = p >> 6, j = p & 63;
        float a = 0.0f;
#pragma unroll
        for (int r = 0; r < 8; r++) a += sEf[e * 8 + r] * R[r * 64 + j];
        sH[p] = silu_n(a);
    }
    __syncthreads();

    // -------- layers 1,2 (64 -> 64), transposed W, 4-edge register tile ----
    {
        int eg1 = tid >> 6;         // 0..3, 4 edges each
        int j1  = tid & 63;
        float acc4[4];
#pragma unroll
        for (int e = 0; e < 4; e++) acc4[e] = 0.0f;
#pragma unroll 4
        for (int hh = 0; hh < 64; hh += 4) {
            float4 w4 = F4(&R[512 + j1 * 68 + hh]);
#pragma unroll
            for (int e = 0; e < 4; e++) {
                float4 h4 = F4(&sH[(eg1 * 4 + e) * 64 + hh]);
                acc4[e] += h4.x * w4.x + h4.y * w4.y + h4.z * w4.z + h4.w * w4.w;
            }
        }
        __syncthreads();
#pragma unroll
        for (int e = 0; e < 4; e++)
            sH[1024 + (eg1 * 4 + e) * 64 + j1] = silu_n(acc4[e]);
        __syncthreads();

#pragma unroll
        for (int e = 0; e < 4; e++) acc4[e] = 0.0f;
#pragma unroll 4
        for (int hh = 0; hh < 64; hh += 4) {
            float4 w4 = F4(&R[4864 + j1 * 68 + hh]);
#pragma unroll
            for (int e = 0; e < 4; e++) {
                float4 h4 = F4(&sH[1024 + (eg1 * 4 + e) * 64 + hh]);
                acc4[e] += h4.x * w4.x + h4.y * w4.y + h4.z * w4.z + h4.w * w4.w;
            }
        }
        __syncthreads();
#pragma unroll
        for (int e = 0; e < 4; e++)
            sH[(eg1 * 4 + e) * 64 + j1] = silu_n(acc4[e]);   // h2 -> region 0
    }

    // -------- phase 2: last MLP layer + tensor product --------
    // w3 loaded in quarter chunks (128 cols). Chunk pair (w00,w01) and
    // (w10,w11): first chunk's results kept in registers, combined + stored
    // as packed float4 after the second chunk.
    const float C05 = 0.7071067811865476f;   // sqrt(0.5) (= PW_1O/sqrt(3))
    const float CB0 = 0.4082482904638631f;   // sqrt(1/6)
    int eg = tid >> 5;            // 0..7 -> 2 edges each
    int c4 = (tid & 31) * 4;      // col quad

    for (int pair = 0; pair < 2; pair++) {
        float keepA[2][4];
        for (int sub = 0; sub < 2; sub++) {
            int ch = pair * 2 + sub;
            __syncthreads();      // prior R readers done
            for (int p = tid; p < 8192; p += 256)
                R[p] = w3[(p >> 7) * 512 + ch * 128 + (p & 127)] * 0.125f;
            __syncthreads();

            float4 acc[2];
            acc[0] = make_float4(0.f, 0.f, 0.f, 0.f);
            acc[1] = acc[0];
#pragma unroll 4
            for (int hh = 0; hh < 64; hh += 4) {
                float4 wq0 = F4(&R[(hh + 0) * 128 + c4]);
                float4 wq1 = F4(&R[(hh + 1) * 128 + c4]);
                float4 wq2 = F4(&R[(hh + 2) * 128 + c4]);
                float4 wq3 = F4(&R[(hh + 3) * 128 + c4]);
#pragma unroll
                for (int e = 0; e < 2; e++) {
                    float4 h4 = F4(&sH[(eg * 2 + e) * 64 + hh]);
                    fma4(acc[e], h4.x, wq0); fma4(acc[e], h4.y, wq1);
                    fma4(acc[e], h4.z, wq2); fma4(acc[e], h4.w, wq3);
                }
            }

            if (sub == 0) {
#pragma unroll
                for (int e = 0; e < 2; e++) {
                    keepA[e][0] = acc[e].x; keepA[e][1] = acc[e].y;
                    keepA[e][2] = acc[e].z; keepA[e][3] = acc[e].w;
                }
            } else {
#pragma unroll
                for (int e = 0; e < 2; e++) {
                    int ee = eg * 2 + e;
                    int snd = sSend[ee];
                    float4 sh = F4(&sSh[ee * 4]);
                    float aB[4] = {acc[e].x, acc[e].y, acc[e].z, acc[e].w};
                    if (pair == 0) {   // keepA = w00, aB = w01
                        float4 ss4 = F4(&g_sup[snd * 128 + c4]);
                        float ss[4] = {ss4.x, ss4.y, ss4.z, ss4.w};
#pragma unroll
                        for (int j = 0; j < 4; j++) {
                            float t0 = C05 * sh.x * keepA[e][j] * ss[j];
                            float t1 = C05 * aB[j] * ss[j];
                            ((float4*)sA4)[ee * 256 + c4 + j] =
                                make_float4(t0, t1 * sh.y, t1 * sh.z, t1 * sh.w);
                        }
                    } else {           // keepA = w10, aB = w11
                        float4 x4 = F4(&g_vup[snd * 384 + c4]);
                        float4 y4 = F4(&g_vup[snd * 384 + 128 + c4]);
                        float4 z4 = F4(&g_vup[snd * 384 + 256 + c4]);
                        float vx[4] = {x4.x, x4.y, x4.z, x4.w};
                        float vy[4] = {y4.x, y4.y, y4.z, y4.w};
                        float vz[4] = {z4.x, z4.y, z4.z, z4.w};
#pragma unroll
                        for (int j = 0; j < 4; j++) {
                            float t = C05 * sh.x * keepA[e][j];
                            float d = vx[j] * sh.y + vy[j] * sh.z + vz[j] * sh.w;
                            ((float4*)sA4)[ee * 256 + 128 + c4 + j] =
                                make_float4(CB0 * aB[j] * d,
                                            t * vx[j], t * vy[j], t * vz[j]);
                        }
                    }
                }
            }
        }
    }

    // -------- phase 3: output GEMM (K = 256), 2e x 4c x 4comp tile ---------
    float4 accS[2], accVx[2], accVy[2], accVz[2];
#pragma unroll
    for (int e = 0; e < 2; e++) {
        accS[e]  = make_float4(0.f, 0.f, 0.f, 0.f);
        accVx[e] = accS[e]; accVy[e] = accS[e]; accVz[e] = accS[e];
    }

    for (int kk = 0; kk < 256; kk += 32) {
        __syncthreads();          // at kk=0 also fences phase-2 sA4 writes
        for (int p = tid; p < 4096; p += 256) {
            int kt = p >> 7, cc = p & 127;
            R[p]        = Wos[(kk + kt) * 128 + cc];
            R[4096 + p] = Wov[(kk + kt) * 128 + cc];
        }
        __syncthreads();
#pragma unroll 4
        for (int kt = 0; kt < 32; kt++) {
            float4 ws = F4(&R[kt * 128 + c4]);
            float4 wv = F4(&R[4096 + kt * 128 + c4]);
#pragma unroll
            for (int e = 0; e < 2; e++) {
                float4 a = ((const float4*)sA4)[(eg * 2 + e) * 256 + kk + kt];
                fma4(accS[e],  a.x, ws);
                fma4(accVx[e], a.y, wv);
                fma4(accVy[e], a.z, wv);
                fma4(accVz[e], a.w, wv);
            }
        }
    }

    const float inv16 = 0.0625f;  // 1/sqrt(256)
#pragma unroll
    for (int e = 0; e < 2; e++) {
        size_t row = (size_t)(eb + eg * 2 + e) * 512;
        float4 S = scl4(accS[e],  inv16);
        float4 X = scl4(accVx[e], inv16);
        float4 Y = scl4(accVy[e], inv16);
        float4 Z = scl4(accVz[e], inv16);
        F4W(&out[row + c4]) = S;
        // v layout: out[row + 128 + 3*c + comp]; cols c4..c4+3 -> 12 floats
        F4W(&out[row + 128 + 3 * c4 + 0]) = make_float4(X.x, Y.x, Z.x, X.y);
        F4W(&out[row + 128 + 3 * c4 + 4]) = make_float4(Y.y, Z.y, X.z, Y.z);
        F4W(&out[row + 128 + 3 * c4 + 8]) = make_float4(Z.z, X.w, Y.w, Z.w);
    }
}

extern "C" void kernel_launch(void* const* d_in, const int* in_sizes, int n_in,
                              void* d_out, int out_size) {
    const float* nf  = (const float*)d_in[0];
    const float* ea  = (const float*)d_in[1];
    const float* ef  = (const float*)d_in[2];
    const int*   ei  = (const int*)  d_in[3];
    const float* Wus = (const float*)d_in[4];
    const float* Wuv = (const float*)d_in[5];
    const float* w0  = (const float*)d_in[6];
    const float* w1  = (const float*)d_in[7];
    const float* w2  = (const float*)d_in[8];
    const float* w3  = (const float*)d_in[9];
    const float* Wos = (const float*)d_in[10];
    const float* Wov = (const float*)d_in[11];
    float* out = (float*)d_out;

    const int smem_node = 24576 * 4;   // 96 KB
    const int smem_edge = 27856 * 4;   // ~108.8 KB
    cudaFuncSetAttribute((const void*)node_up_kernel,
                         cudaFuncAttributeMaxDynamicSharedMemorySize, smem_node);
    cudaFuncSetAttribute((const void*)edge_fused_kernel,
                         cudaFuncAttributeMaxDynamicSharedMemorySize, smem_edge);

    node_up_kernel<<<N_NODES / 32, 256, smem_node>>>(nf, Wus, Wuv);
    edge_fused_kernel<<<N_EDGES / EB, 256, smem_edge>>>(ea, ef, ei,
                                                        w0, w1, w2, w3,
                                                        Wos, Wov, out);
}